// round 16
// baseline (speedup 1.0000x reference)
#include <cuda_runtime.h>

#define BB 16
#define CC 9
#define LL 1024
#define DD 16
#define HH 8
#define NCLS 10

typedef unsigned long long u64;

// ---------------- scratch (zero-initialized at load; each replay re-zeroes for the next) ----
__device__ float g_h2[BB*LL*DD];       // conv2 accum (bias-free) [b][l][d]
__device__ float g_xsrc[BB*LL*DD];     // post bn2+gelu [b][l][d]
__device__ float g_q[BB*HH*LL*2];      // float2 per (bh,l), pre-scaled 0.25*log2e
__device__ float g_soa[BB*HH*LL*4];    // per bh: k-interleaved[2048] | v-interleaved[2048]
__device__ float g_o[BB*LL*DD];        // attention output (softmax@V/l + bias@V)
__device__ float g_w2t[CC*DD*64];      // [c][d][i]
__device__ float g_s1sum[64], g_s1sq[64];
__device__ float g_s2sum[DD], g_s2sq[DD];
__device__ float g_pool[BB*DD];
__device__ unsigned g_done;            // k_post completion counter
__device__ unsigned g_done2;           // k_qkv stats barrier counter

__device__ __forceinline__ float ex2f(float x) {
    float e; asm("ex2.approx.f32 %0, %1;" : "=f"(e) : "f"(x)); return e;
}
__device__ __forceinline__ u64 pk2(float lo, float hi) {
    u64 r; asm("mov.b64 %0, {%1,%2};" : "=l"(r) : "f"(lo), "f"(hi)); return r;
}
__device__ __forceinline__ void upk2(u64 a, float& lo, float& hi) {
    asm("mov.b64 {%0,%1}, %2;" : "=f"(lo), "=f"(hi) : "l"(a));
}
__device__ __forceinline__ u64 fma2_(u64 a, u64 b, u64 c) {
    u64 d; asm("fma.rn.f32x2 %0, %1, %2, %3;" : "=l"(d) : "l"(a), "l"(b), "l"(c)); return d;
}
__device__ __forceinline__ u64 add2_(u64 a, u64 b) {
    u64 d; asm("add.rn.f32x2 %0, %1, %2;" : "=l"(d) : "l"(a), "l"(b)); return d;
}
// branch-free gelu via A&S 7.1.26 erf (|err| <= 1.5e-7)
__device__ __forceinline__ float gelu(float x) {
    float z = fabsf(x) * 0.70710678118654752f;
    float t; asm("rcp.approx.f32 %0, %1;" : "=f"(t) : "f"(fmaf(0.3275911f, z, 1.0f)));
    float p = fmaf(t, 1.061405429f, -1.453152027f);
    p = fmaf(t, p, 1.421413741f);
    p = fmaf(t, p, -0.284496736f);
    p = fmaf(t, p, 0.254829592f);
    p = p * t;
    float e = ex2f(z * z * -1.4426950408889634f);
    float r = fmaf(-p, e, 1.0f);
    return fmaf(0.5f * fabsf(x), r, 0.5f * x);
}

// ---------------- pre: conv1 stats (x2 l-split) + transpose w2 ----------------
// grid 324 = stats(288) | w2t(36)     (g_h2 arrives zeroed from previous replay / load)
__global__ void k_pre(const float* __restrict__ x, const float* __restrict__ w1,
                      const float* __restrict__ w2) {
    __shared__ float sXe[520];
    int bx = blockIdx.x, tid = threadIdx.x;
    if (bx < 288) {
        int b = bx / 18, r = bx % 18, c = r >> 1, half = r & 1;
        int l0 = half << 9;
        for (int j = tid; j < 519; j += 256) {
            int l = l0 - 3 + j;
            sXe[j] = (l >= 0 && l < LL) ? __ldg(&x[(b*CC + c)*LL + l]) : 0.f;
        }
        __syncthreads();
        int o = tid >> 2, sub = tid & 3;
        float w[8];
#pragma unroll
        for (int k = 0; k < 8; k++) w[k] = __ldg(&w1[o*8 + k]);
        float s = 0.f, sq = 0.f;
#pragma unroll 4
        for (int li = 0; li < 128; li++) {
            int l = sub + li*4;
            float a = 0.f;
#pragma unroll
            for (int k = 0; k < 8; k++) a = fmaf(w[k], sXe[l + k], a);
            s += a; sq = fmaf(a, a, sq);
        }
        s  += __shfl_down_sync(0xffffffffu, s, 2, 4);
        s  += __shfl_down_sync(0xffffffffu, s, 1, 4);
        sq += __shfl_down_sync(0xffffffffu, sq, 2, 4);
        sq += __shfl_down_sync(0xffffffffu, sq, 1, 4);
        if (sub == 0) { atomicAdd(&g_s1sum[o], s); atomicAdd(&g_s1sq[o], sq); }
    } else {
        int e = (bx - 288)*256 + tid;   // 0..9215
        int c = e >> 10, r = e & 1023, d = r >> 6, i = r & 63;
        g_w2t[e] = __ldg(&w2[d*576 + i*9 + c]);
    }
}

// ---------------- fused conv1->bn1->gelu->conv2 (c-split x9, 128-l tile, dual-d, f32x2) ----
// grid 1152 = b(16) x lt(8 of 128) x c(9); 256 thr; fin1 recomputed per block
__global__ void __launch_bounds__(256, 2)
k_fused(const float* __restrict__ x, const float* __restrict__ w1,
        const float* __restrict__ bn1g, const float* __restrict__ bn1b) {
    __shared__ float sX[136];
    __shared__ float sW1[512];
    __shared__ float sS[64], sT[64];
    __shared__ float sA[64*132];     // [i][l], stride 132 (33 float4s, conflict-free)
    __shared__ float sW2c[1024];
    int bx = blockIdx.x;
    int c = bx % 9; int tmp = bx / 9; int lt = tmp & 7; int b = tmp >> 3;
    int l0 = lt << 7;                // 128 l per block
    int tid = threadIdx.x;
    if (tid < 135) {
        int l = l0 - 3 + tid;
        sX[tid] = (l >= 0 && l < LL) ? __ldg(&x[(b*CC + c)*LL + l]) : 0.f;
    }
    for (int e = tid; e < 512; e += 256) sW1[e] = __ldg(&w1[e]);
    *(float4*)&sW2c[tid*4] = *(const float4*)&g_w2t[c*1024 + tid*4];
    if (tid < 64) {
        const float invN = 1.f / 147456.f;
        float mean = g_s1sum[tid] * invN;
        float var  = g_s1sq[tid] * invN - mean*mean;
        float sc = __ldg(&bn1g[tid]) * rsqrtf(var + 1e-5f);
        sS[tid] = sc;
        sT[tid] = __ldg(&bn1b[tid]) - mean * sc;
    }
    __syncthreads();
    // activation: thread owns an l-PAIR (x window in 9 regs) x 16 i's
    {
        int lp = tid & 63, ig = tid >> 6;   // 64 l-pairs x 4 i-groups
        int lb = lp << 1;
        float xw[9];
#pragma unroll
        for (int k = 0; k < 9; k++) xw[k] = sX[lb + k];
#pragma unroll
        for (int ii = 0; ii < 16; ii++) {
            int i = ig*16 + ii;
            const float* wr = &sW1[i*8];
            float a0 = 0.f, a1 = 0.f;
#pragma unroll
            for (int k = 0; k < 8; k++) {
                float w = wr[k];
                a0 = fmaf(w, xw[k], a0);
                a1 = fmaf(w, xw[k + 1], a1);
            }
            float sc = sS[i], sh = sT[i];
            a0 = fmaf(a0, sc, sh);
            a1 = fmaf(a1, sc, sh);
            *(float2*)&sA[i*132 + lb] = make_float2(gelu(a0), gelu(a1));
        }
    }
    __syncthreads();
    // conv2 partial GEMM: thread = (d-pair, l-quad of 32); f32x2 packed over l-pairs
    int dp = tid >> 5, lg = tid & 31;
    int d0 = dp*2, d1 = d0 + 1;
    u64 a00 = 0, a01 = 0, a10 = 0, a11 = 0;   // [d0|d1][lpair 01|23]
    const float4* wrow0 = (const float4*)&sW2c[d0*64];
    const float4* wrow1 = (const float4*)&sW2c[d1*64];
    const float* ab0 = &sA[lg*4];
#pragma unroll
    for (int j = 0; j < 16; j++) {
        float4 w40 = wrow0[j];
        float4 w41 = wrow1[j];
        const float* ab = ab0 + j*4*132;
#pragma unroll
        for (int s = 0; s < 4; s++) {
            longlong2 av = *(const longlong2*)(ab + s*132);
            float w0 = (s == 0) ? w40.x : (s == 1) ? w40.y : (s == 2) ? w40.z : w40.w;
            float w1v = (s == 0) ? w41.x : (s == 1) ? w41.y : (s == 2) ? w41.z : w41.w;
            u64 w0p = pk2(w0, w0), w1p = pk2(w1v, w1v);
            a00 = fma2_(w0p, (u64)av.x, a00);
            a01 = fma2_(w0p, (u64)av.y, a01);
            a10 = fma2_(w1p, (u64)av.x, a10);
            a11 = fma2_(w1p, (u64)av.y, a11);
        }
    }
    float x0, x1, x2, x3, y0, y1, y2, y3;
    upk2(a00, x0, x1); upk2(a01, x2, x3);
    upk2(a10, y0, y1); upk2(a11, y2, y3);
    int baseo = (b*LL + l0 + lg*4)*DD;
    atomicAdd(&g_h2[baseo + d0     ], x0);
    atomicAdd(&g_h2[baseo + d0 + 16], x1);
    atomicAdd(&g_h2[baseo + d0 + 32], x2);
    atomicAdd(&g_h2[baseo + d0 + 48], x3);
    atomicAdd(&g_h2[baseo + d1     ], y0);
    atomicAdd(&g_h2[baseo + d1 + 16], y1);
    atomicAdd(&g_h2[baseo + d1 + 32], y2);
    atomicAdd(&g_h2[baseo + d1 + 48], y3);
}

// ---------------- inline BN2 stats + spin barrier + bn2+gelu + pos-enc + QKV (f32x2) -------
// grid 256 x 256 (all blocks co-resident: <=3.4KB smem); 4 threads/token (2 heads each)
// also re-zeroes its own g_h2 slice after consumption (for the next replay)
__global__ void k_qkv(const float* __restrict__ wq, const float* __restrict__ wk,
                      const float* __restrict__ wv,
                      const float* __restrict__ bn2g, const float* __restrict__ bn2b) {
    __shared__ float sq_[256], sk_[256], sv_[256], s2s[16], s2t[16];
    __shared__ float sS2[16], sQ2[16];
    int tid = threadIdx.x;
    // ---- phase 1: partial BN2 stats over this block's slice of g_h2 ----
    if (tid < 16) { sS2[tid] = 0.f; sQ2[tid] = 0.f; }
    __syncthreads();
    {
        int gid = blockIdx.x*256 + tid;          // 0..65535 float4s
        float4 hv = ((const float4*)g_h2)[gid];
        float s0 = hv.x, s1 = hv.y, s2 = hv.z, s3 = hv.w;
        float q0 = hv.x*hv.x, q1 = hv.y*hv.y, q2 = hv.z*hv.z, q3 = hv.w*hv.w;
#pragma unroll
        for (int off = 4; off <= 16; off <<= 1) {
            s0 += __shfl_down_sync(0xffffffffu, s0, off);
            s1 += __shfl_down_sync(0xffffffffu, s1, off);
            s2 += __shfl_down_sync(0xffffffffu, s2, off);
            s3 += __shfl_down_sync(0xffffffffu, s3, off);
            q0 += __shfl_down_sync(0xffffffffu, q0, off);
            q1 += __shfl_down_sync(0xffffffffu, q1, off);
            q2 += __shfl_down_sync(0xffffffffu, q2, off);
            q3 += __shfl_down_sync(0xffffffffu, q3, off);
        }
        if ((tid & 31) < 4) {
            int db = (tid & 3) * 4;
            atomicAdd(&sS2[db    ], s0); atomicAdd(&sQ2[db    ], q0);
            atomicAdd(&sS2[db + 1], s1); atomicAdd(&sQ2[db + 1], q1);
            atomicAdd(&sS2[db + 2], s2); atomicAdd(&sQ2[db + 2], q2);
            atomicAdd(&sS2[db + 3], s3); atomicAdd(&sQ2[db + 3], q3);
        }
    }
    __syncthreads();
    if (tid < 16) { atomicAdd(&g_s2sum[tid], sS2[tid]); atomicAdd(&g_s2sq[tid], sQ2[tid]); }
    // ---- spin barrier across all 256 resident blocks ----
    __syncthreads();
    if (tid == 0) {
        __threadfence();
        atomicAdd(&g_done2, 1u);
        while (*(volatile unsigned*)&g_done2 < 256u) { }
    }
    __syncthreads();
    __threadfence();
    // ---- phase 2: weights + bn2 finalize ----
    sq_[tid] = __ldg(&wq[tid]); sk_[tid] = __ldg(&wk[tid]); sv_[tid] = __ldg(&wv[tid]);
    if (tid < 16) {
        const float invN = 1.f / 16384.f;
        float mean = g_s2sum[tid] * invN;
        float var  = g_s2sq[tid] * invN - mean*mean;
        float sc = __ldg(&bn2g[tid]) * rsqrtf(var + 1e-5f);
        s2s[tid] = sc;
        s2t[tid] = __ldg(&bn2b[tid]) - mean * sc;
    }
    __syncthreads();
    int sub = tid & 3;
    int t = blockIdx.x*64 + (tid >> 2);
    int l = t & 1023, b = t >> 10;
    float xp[16];
    const float4* hr = (const float4*)&g_h2[t*DD];
    float4* xsr = (float4*)&g_xsrc[t*DD];
#pragma unroll
    for (int i = 0; i < 4; i++) {
        float4 h4 = hr[i];
        float vs[4] = {h4.x, h4.y, h4.z, h4.w};
#pragma unroll
        for (int j = 0; j < 4; j++) {
            int d = i*4 + j;
            float v = gelu(fmaf(vs[j], s2s[d], s2t[d]));
            vs[j] = v; xp[d] = v;
        }
        if (sub == 0) xsr[i] = make_float4(vs[0], vs[1], vs[2], vs[3]);
    }
    // re-zero own g_h2 float4 (this thread's sub slice) for the next replay
    ((float4*)&g_h2[t*DD])[sub] = make_float4(0.f, 0.f, 0.f, 0.f);
    const float divc[8] = {1.f, 0.31622776601683794f, 0.1f, 0.031622776601683794f,
                           0.01f, 0.0031622776601683794f, 0.001f, 0.00031622776601683794f};
    float lf = (float)l;
#pragma unroll
    for (int j = 0; j < 8; j++) {
        float ang = lf * divc[j] * 0.015625f;
        float sv, cv; __sincosf(ang, &sv, &cv);
        xp[2*j]   += sv;
        xp[2*j+1] += cv;
    }
    const float QS = 0.36067376022224085f;  // 0.25 * log2(e)
    // packed projections: weight h-pairs are u64-adjacent; both heads share xvp
    {
        int h0 = sub*2, h1 = h0 + 1;
        const u64* wqp = (const u64*)sq_;
        const u64* wkp = (const u64*)sk_;
        const u64* wvp = (const u64*)sv_;
        u64 qpa = 0, kpa = 0, vpa = 0, qpb = 0, kpb = 0, vpb = 0;
#pragma unroll
        for (int e = 0; e < 16; e++) {
            u64 xvp = pk2(xp[e], xp[e]);
            qpa = fma2_(xvp, wqp[e*8 + h0], qpa);
            kpa = fma2_(xvp, wkp[e*8 + h0], kpa);
            vpa = fma2_(xvp, wvp[e*8 + h0], vpa);
            qpb = fma2_(xvp, wqp[e*8 + h1], qpb);
            kpb = fma2_(xvp, wkp[e*8 + h1], kpb);
            vpb = fma2_(xvp, wvp[e*8 + h1], vpb);
        }
        int pk = l >> 1, e2 = l & 1;
#pragma unroll
        for (int hh = 0; hh < 2; hh++) {
            float q0, q1, k0, k1, v0, v1;
            if (hh == 0) { upk2(qpa, q0, q1); upk2(kpa, k0, k1); upk2(vpa, v0, v1); }
            else         { upk2(qpb, q0, q1); upk2(kpb, k0, k1); upk2(vpb, v0, v1); }
            int h = h0 + hh;
            int bh = b*8 + h;
            float* sb = &g_soa[bh*4096];
            // interleaved: k-int[pk] = (kx_e, kx_o, ky_e, ky_o); v-int at +2048
            sb[pk*4 + e2]            = k0;
            sb[pk*4 + 2 + e2]        = k1;
            sb[2048 + pk*4 + e2]     = v0;
            sb[2048 + pk*4 + 2 + e2] = v1;
            ((float2*)g_q)[bh*1024 + l] = make_float2(q0*QS, q1*QS);
        }
    }
}

// ---------------- attention: softmax(q.k/4)@V + bias@V in ONE loop ----------------
// grid 512 = bh(128) x qtile(4 of 256); 256 thr; one q per thread
// pair-interleaved smem: one LDS.128 yields both k-u64s (or both v-u64s)
__global__ void k_attn(const float* __restrict__ rel) {
    __shared__ float4 skI[512], svI[512];
    __shared__ float2 sr0[640], sr1[640];
    __shared__ float sred[16];
    int bx = blockIdx.x;
    int tile = bx & 3, bh = bx >> 2, h = bh & 7, b = bh >> 3;
    int q0 = tile << 8;
    int tid = threadIdx.x;
    const float4* base = (const float4*)&g_soa[bh*4096];
    float4 k0v = base[tid];
    skI[tid] = k0v;
    float mk0 = fmaxf(fabsf(k0v.x), fabsf(k0v.y));
    float mk1 = fmaxf(fabsf(k0v.z), fabsf(k0v.w));
    float4 k1v = base[256 + tid];
    skI[256 + tid] = k1v;
    mk0 = fmaxf(mk0, fmaxf(fabsf(k1v.x), fabsf(k1v.y)));
    mk1 = fmaxf(mk1, fmaxf(fabsf(k1v.z), fabsf(k1v.w)));
    svI[tid]       = base[512 + tid];
    svI[256 + tid] = base[768 + tid];
    // rel pairs, parity-preswapped: srel[i] := rel[(q0+i)*8+h], i in [0,1279)
    for (int s = tid; s < 640; s += 256) {
        int i2 = 2*s;
        float r0 = (i2     < 1279) ? __ldg(&rel[(q0 + i2    )*8 + h]) : 0.f;
        float r1 = (i2 + 1 < 1279) ? __ldg(&rel[(q0 + i2 + 1)*8 + h]) : 0.f;
        float r2 = (i2 + 2 < 1279) ? __ldg(&rel[(q0 + i2 + 2)*8 + h]) : 0.f;
        sr0[s] = make_float2(r1, r0);
        sr1[s] = make_float2(r2, r1);
    }
#pragma unroll
    for (int off = 16; off; off >>= 1) {
        mk0 = fmaxf(mk0, __shfl_xor_sync(0xffffffffu, mk0, off));
        mk1 = fmaxf(mk1, __shfl_xor_sync(0xffffffffu, mk1, off));
    }
    if ((tid & 31) == 0) { sred[tid >> 5] = mk0; sred[8 + (tid >> 5)] = mk1; }
    __syncthreads();
    float K0 = sred[0], K1 = sred[8];
#pragma unroll
    for (int i = 1; i < 8; i++) { K0 = fmaxf(K0, sred[i]); K1 = fmaxf(K1, sred[8+i]); }

    float2 qq = ((const float2*)g_q)[(bh << 10) + q0 + tid];
    float m = fabsf(qq.x)*K0 + fabsf(qq.y)*K1;   // upper bound; shift cancels in acc/l
    u64 qx2 = pk2(qq.x, qq.x), qy2 = pk2(qq.y, qq.y), negm2 = pk2(-m, -m);
    u64 l2 = 0, a0 = 0, a1 = 0, c0 = 0, c1 = 0;
    int p = tid & 1;
    int roff = ((tid - p) >> 1) + 511;
    const float2* srp = p ? sr1 : sr0;
    const longlong2* skp = (const longlong2*)skI;
    const longlong2* svp = (const longlong2*)svI;
#pragma unroll 4
    for (int kk = 0; kk < 512; kk++) {
        longlong2 kp = skp[kk];                   // LDS.128: kx-pair | ky-pair
        longlong2 vp = svp[kk];                   // LDS.128: vx-pair | vy-pair
        u64 s2 = fma2_(qy2, (u64)kp.y, fma2_(qx2, (u64)kp.x, negm2));
        float s0, s1; upk2(s2, s0, s1);
        u64 e2 = pk2(ex2f(s0), ex2f(s1));
        l2 = add2_(l2, e2);
        a0 = fma2_(e2, (u64)vp.x, a0);
        a1 = fma2_(e2, (u64)vp.y, a1);
        u64 r2 = *(const u64*)&srp[roff - kk];
        c0 = fma2_(r2, (u64)vp.x, c0);
        c1 = fma2_(r2, (u64)vp.y, c1);
    }
    float p0, p1;
    upk2(l2, p0, p1); float inv = 1.f / (p0 + p1);
    upk2(a0, p0, p1); float A0 = p0 + p1;
    upk2(a1, p0, p1); float A1 = p0 + p1;
    upk2(c0, p0, p1); float C0 = p0 + p1;
    upk2(c1, p0, p1); float C1 = p0 + p1;
    int ti = b*LL + q0 + tid;
    *(float2*)&g_o[ti*DD + 2*h] =
        make_float2(fmaf(A0, inv, C0), fmaf(A1, inv, C1));
}

// ---------------- LN_attn + res + LN1 + FFN(j-split x4, f32x2) + res + LN2 + pool + final --
// grid 256 x 256; 4 threads per token; last block computes the classifier output
// and re-zeroes all small accumulators for the next replay
__global__ void k_post(const float* __restrict__ w1, const float* __restrict__ b1,
                       const float* __restrict__ w2, const float* __restrict__ b2,
                       const float* __restrict__ lag, const float* __restrict__ lab,
                       const float* __restrict__ l1g, const float* __restrict__ l1b,
                       const float* __restrict__ l2g, const float* __restrict__ l2b,
                       const float* __restrict__ ow, const float* __restrict__ ob,
                       float* __restrict__ out) {
    __shared__ float sW1T[4096];  // [j][d]
    __shared__ float sW2[4096];   // [j][d]
    __shared__ float sB1[256], sPool[16], sLn[112];
    __shared__ unsigned sLast;
    int tid = threadIdx.x;
    for (int i = tid; i < 4096; i += 256) {
        sW1T[(i & 255)*16 + (i >> 8)] = __ldg(&w1[i]);
        sW2[i] = __ldg(&w2[i]);
    }
    sB1[tid] = __ldg(&b1[tid]);
    if (tid < 16) {
        sPool[tid] = 0.f;
        sLn[tid]      = __ldg(&lag[tid]); sLn[16 + tid] = __ldg(&lab[tid]);
        sLn[32 + tid] = __ldg(&l1g[tid]); sLn[48 + tid] = __ldg(&l1b[tid]);
        sLn[64 + tid] = __ldg(&l2g[tid]); sLn[80 + tid] = __ldg(&l2b[tid]);
        sLn[96 + tid] = __ldg(&b2[tid]);
    }
    __syncthreads();
    int sub = tid & 3;
    int t = blockIdx.x*64 + (tid >> 2);
    float v[16], xs[16], att[16], acc[16];
    const float4* orow = (const float4*)&g_o[t*DD];
    const float4* xrow = (const float4*)&g_xsrc[t*DD];
#pragma unroll
    for (int i = 0; i < 4; i++) {
        float4 f = orow[i]; v[4*i]=f.x; v[4*i+1]=f.y; v[4*i+2]=f.z; v[4*i+3]=f.w;
        float4 g = xrow[i]; xs[4*i]=g.x; xs[4*i+1]=g.y; xs[4*i+2]=g.z; xs[4*i+3]=g.w;
    }
    float mean = 0.f, sq = 0.f;
#pragma unroll
    for (int d = 0; d < 16; d++) { mean += v[d]; sq = fmaf(v[d], v[d], sq); }
    mean *= 0.0625f;
    float rs = rsqrtf(sq*0.0625f - mean*mean + 1e-5f);
    float m2 = 0.f, q2 = 0.f;
#pragma unroll
    for (int d = 0; d < 16; d++) {
        float x1 = xs[d] + fmaf((v[d]-mean)*rs, sLn[d], sLn[16+d]);
        v[d] = x1; m2 += x1; q2 = fmaf(x1, x1, q2);
    }
    m2 *= 0.0625f;
    float rs2 = rsqrtf(q2*0.0625f - m2*m2 + 1e-5f);
#pragma unroll
    for (int d = 0; d < 16; d++)
        att[d] = fmaf((v[d]-m2)*rs2, sLn[32+d], sLn[48+d]);
    // packed FFN
    u64 attp[8], accp[8];
#pragma unroll
    for (int i = 0; i < 8; i++) { attp[i] = pk2(att[2*i], att[2*i+1]); accp[i] = 0; }
    int j0 = sub << 6;
#pragma unroll 2
    for (int jj = 0; jj < 64; jj++) {
        int j = j0 + jj;
        const u64* w1r = (const u64*)&sW1T[j*16];
        u64 hp = 0;
#pragma unroll
        for (int i = 0; i < 8; i++) hp = fma2_(attp[i], w1r[i], hp);
        float h0, h1; upk2(hp, h0, h1);
        float hv = fmaxf(sB1[j] + h0 + h1, 0.f);
        u64 hvp = pk2(hv, hv);
        const u64* w2r = (const u64*)&sW2[j*16];
#pragma unroll
        for (int i = 0; i < 8; i++) accp[i] = fma2_(hvp, w2r[i], accp[i]);
    }
#pragma unroll
    for (int i = 0; i < 8; i++) upk2(accp[i], acc[2*i], acc[2*i+1]);
#pragma unroll
    for (int d = 0; d < 16; d++) {
        acc[d] += __shfl_xor_sync(0xffffffffu, acc[d], 1);
        acc[d] += __shfl_xor_sync(0xffffffffu, acc[d], 2);
    }
    float m3 = 0.f, q3 = 0.f;
#pragma unroll
    for (int d = 0; d < 16; d++) {
        float x2 = att[d] + acc[d] + sLn[96+d];
        v[d] = x2; m3 += x2; q3 = fmaf(x2, x2, q3);
    }
    m3 *= 0.0625f;
    float rs3 = rsqrtf(q3*0.0625f - m3*m3 + 1e-5f);
    if (sub == 0) {
#pragma unroll
        for (int d = 0; d < 16; d++) {
            float fin = fmaf((v[d]-m3)*rs3, sLn[64+d], sLn[80+d]);
            atomicAdd(&sPool[d], fin);
        }
    }
    __syncthreads();
    if (tid < 16) atomicAdd(&g_pool[(blockIdx.x >> 4)*16 + tid], sPool[tid]);
    // ---- completion counter: last block computes the classifier + resets state ----
    __threadfence();
    __syncthreads();
    if (tid == 0) sLast = (atomicAdd(&g_done, 1u) == 255u) ? 1u : 0u;
    __syncthreads();
    if (sLast) {
        if (tid < BB*NCLS) {
            int b = tid / NCLS, n = tid % NCLS;
            float a = __ldg(&ob[n]);
#pragma unroll
            for (int d = 0; d < 16; d++) {
                float pv = atomicAdd(&g_pool[b*16 + d], 0.f);   // coherent read
                a = fmaf(pv * 0.0009765625f, __ldg(&ow[d*NCLS + n]), a);
            }
            out[tid] = a;
        }
        __syncthreads();
        // re-zero all small accumulators for the next graph replay
        g_pool[tid] = 0.f;
        if (tid < 64) { g_s1sum[tid] = 0.f; g_s1sq[tid] = 0.f; }
        if (tid < DD) { g_s2sum[tid] = 0.f; g_s2sq[tid] = 0.f; }
        if (tid == 0) { g_done2 = 0u; __threadfence(); g_done = 0u; }
    }
}

// ---------------- launch ----------------
extern "C" void kernel_launch(void* const* d_in, const int* in_sizes, int n_in,
                              void* d_out, int out_size) {
    const float* x    = (const float*)d_in[0];
    const float* c1w  = (const float*)d_in[1];
    const float* bn1g = (const float*)d_in[3];
    const float* bn1b = (const float*)d_in[4];
    const float* c2w  = (const float*)d_in[5];
    const float* bn2g = (const float*)d_in[7];
    const float* bn2b = (const float*)d_in[8];
    const float* wq   = (const float*)d_in[9];
    const float* wk   = (const float*)d_in[10];
    const float* wv   = (const float*)d_in[11];
    const float* rel  = (const float*)d_in[12];
    const float* lag  = (const float*)d_in[13];
    const float* lab  = (const float*)d_in[14];
    const float* l1g  = (const float*)d_in[15];
    const float* l1b  = (const float*)d_in[16];
    const float* fw1  = (const float*)d_in[17];
    const float* fb1  = (const float*)d_in[18];
    const float* fw2  = (const float*)d_in[19];
    const float* fb2  = (const float*)d_in[20];
    const float* l2g  = (const float*)d_in[21];
    const float* l2b  = (const float*)d_in[22];
    const float* ow   = (const float*)d_in[23];
    const float* ob   = (const float*)d_in[24];

    k_pre   <<<324, 256>>>(x, c1w, c2w);
    k_fused <<<1152, 256>>>(x, c1w, bn1g, bn1b);
    k_qkv   <<<256, 256>>>(wq, wk, wv, bn2g, bn2b);
    k_attn  <<<512, 256>>>(rel);
    k_post  <<<256, 256>>>(fw1, fb1, fw2, fb2, lag, lab, l1g, l1b, l2g, l2b,
                           ow, ob, (float*)d_out);
}

// round 17
// speedup vs baseline: 1.0368x; 1.0368x over previous
#include <cuda_runtime.h>

#define BB 16
#define CC 9
#define LL 1024
#define DD 16
#define HH 8
#define NCLS 10

typedef unsigned long long u64;

// ---------------- scratch (zero-initialized at load; each replay re-zeroes for the next) ----
__device__ float g_h2[BB*LL*DD];       // conv2 accum (bias-free) [b][l][d]
__device__ float g_xsrc[BB*LL*DD];     // post bn2+gelu [b][l][d]
__device__ float g_q[BB*HH*LL*2];      // float2 per (bh,l), pre-scaled 0.25*log2e
__device__ float g_soa[BB*HH*LL*4];    // per bh: k-interleaved[2048] | v-interleaved[2048]
__device__ float g_o[BB*LL*DD];        // attention output (softmax@V/l + bias@V)
__device__ float g_w2t[CC*DD*64];      // [c][d][i]
__device__ float g_T[8];               // BN1: summed clipped window-sums of x
__device__ float g_M[64];              // BN1: summed window Gram matrix (upper tri at [j*8+k])
__device__ float g_s2sum[DD], g_s2sq[DD];
__device__ float g_pool[BB*DD];
__device__ unsigned g_done;            // k_post completion counter
__device__ unsigned g_done2;           // k_qkv stats barrier counter

__device__ __forceinline__ float ex2f(float x) {
    float e; asm("ex2.approx.f32 %0, %1;" : "=f"(e) : "f"(x)); return e;
}
__device__ __forceinline__ u64 pk2(float lo, float hi) {
    u64 r; asm("mov.b64 %0, {%1,%2};" : "=l"(r) : "f"(lo), "f"(hi)); return r;
}
__device__ __forceinline__ void upk2(u64 a, float& lo, float& hi) {
    asm("mov.b64 {%0,%1}, %2;" : "=f"(lo), "=f"(hi) : "l"(a));
}
__device__ __forceinline__ u64 fma2_(u64 a, u64 b, u64 c) {
    u64 d; asm("fma.rn.f32x2 %0, %1, %2, %3;" : "=l"(d) : "l"(a), "l"(b), "l"(c)); return d;
}
__device__ __forceinline__ u64 add2_(u64 a, u64 b) {
    u64 d; asm("add.rn.f32x2 %0, %1, %2;" : "=l"(d) : "l"(a), "l"(b)); return d;
}
// branch-free gelu via A&S 7.1.26 erf (|err| <= 1.5e-7)
__device__ __forceinline__ float gelu(float x) {
    float z = fabsf(x) * 0.70710678118654752f;
    float t; asm("rcp.approx.f32 %0, %1;" : "=f"(t) : "f"(fmaf(0.3275911f, z, 1.0f)));
    float p = fmaf(t, 1.061405429f, -1.453152027f);
    p = fmaf(t, p, 1.421413741f);
    p = fmaf(t, p, -0.284496736f);
    p = fmaf(t, p, 0.254829592f);
    p = p * t;
    float e = ex2f(z * z * -1.4426950408889634f);
    float r = fmaf(-p, e, 1.0f);
    return fmaf(0.5f * fabsf(x), r, 0.5f * x);
}

// ---------------- pre: BN1 moments via autocorrelation + transpose w2 ----------------
// grid 180 = stats(144: one per (b,c)) | w2t(36)
// Stats: y = conv1(x) (bias-free). Sum y[o] = sum_k w[o,k] T_k; Sum y^2[o] = w^T M w,
// with T_k clipped window sums and M_jk = A_{k-j} - edge corrections.
__global__ void k_pre(const float* __restrict__ x, const float* __restrict__ w1,
                      const float* __restrict__ w2) {
    __shared__ float sXe[1032];
    __shared__ float sRed[8*9];
    __shared__ float sA9[9];     // [0]=S, [1+d]=A_d
    int bx = blockIdx.x, tid = threadIdx.x;
    if (bx < 144) {
        int b = bx / 9, c = bx % 9;
        for (int j = tid; j < 1032; j += 256)
            sXe[j] = (j < 1024) ? __ldg(&x[(b*CC + c)*LL + j]) : 0.f;
        __syncthreads();
        int m0 = tid * 4;
        float S = 0.f, A[8];
#pragma unroll
        for (int d = 0; d < 8; d++) A[d] = 0.f;
#pragma unroll
        for (int i = 0; i < 4; i++) {
            float xm = sXe[m0 + i];
            S += xm;
#pragma unroll
            for (int d = 0; d < 8; d++) A[d] = fmaf(xm, sXe[m0 + i + d], A[d]);
        }
#pragma unroll
        for (int off = 16; off; off >>= 1) {
            S += __shfl_down_sync(0xffffffffu, S, off);
#pragma unroll
            for (int d = 0; d < 8; d++) A[d] += __shfl_down_sync(0xffffffffu, A[d], off);
        }
        int lane = tid & 31, w = tid >> 5;
        if (lane == 0) {
            sRed[w*9] = S;
#pragma unroll
            for (int d = 0; d < 8; d++) sRed[w*9 + 1 + d] = A[d];
        }
        __syncthreads();
        if (tid < 9) {
            float t = 0.f;
#pragma unroll
            for (int i = 0; i < 8; i++) t += sRed[i*9 + tid];
            sA9[tid] = t;
        }
        __syncthreads();
        if (tid < 64) {
            int j = tid >> 3, k = tid & 7;
            if (j <= k) {
                int d = k - j;
                float C = 0.f;
                if (j >= 4)
                    for (int m = 0; m <= j - 4; m++) C += sXe[m] * sXe[m + d];
                if (k <= 2)
                    for (int m = 1021 + j; m <= 1023 - d; m++) C += sXe[m] * sXe[m + d];
                atomicAdd(&g_M[j*8 + k], sA9[1 + d] - C);
            }
        }
        if (tid >= 64 && tid < 72) {
            int k = tid - 64;
            float T = sA9[0];
            if (k < 3)  for (int m = 1021 + k; m <= 1023; m++) T -= sXe[m];
            if (k > 3)  for (int m = 0; m <= k - 4; m++)       T -= sXe[m];
            atomicAdd(&g_T[k], T);
        }
    } else {
        int e = (bx - 144)*256 + tid;   // 0..9215
        int c = e >> 10, r = e & 1023, d = r >> 6, i = r & 63;
        g_w2t[e] = __ldg(&w2[d*576 + i*9 + c]);
    }
}

// ---------------- fused conv1->bn1->gelu->conv2 (c-split x9, 128-l tile, dual-d) ----------
// grid 1152 = b(16) x lt(8 of 128) x c(9); 256 thr; BN1 finalize from (w, T, M) per block
__global__ void __launch_bounds__(256, 2)
k_fused(const float* __restrict__ x, const float* __restrict__ w1,
        const float* __restrict__ bn1g, const float* __restrict__ bn1b) {
    __shared__ float sX[136];
    __shared__ float sW1[512];
    __shared__ float sS[64], sT[64];
    __shared__ float sMf[64], sTv[8];
    __shared__ float sA[64*132];     // [i][l], stride 132 (33 float4s, conflict-free)
    __shared__ float sW2c[1024];
    int bx = blockIdx.x;
    int c = bx % 9; int tmp = bx / 9; int lt = tmp & 7; int b = tmp >> 3;
    int l0 = lt << 7;                // 128 l per block
    int tid = threadIdx.x;
    if (tid < 135) {
        int l = l0 - 3 + tid;
        sX[tid] = (l >= 0 && l < LL) ? __ldg(&x[(b*CC + c)*LL + l]) : 0.f;
    }
    for (int e = tid; e < 512; e += 256) sW1[e] = __ldg(&w1[e]);
    *(float4*)&sW2c[tid*4] = *(const float4*)&g_w2t[c*1024 + tid*4];
    if (tid < 64) {
        int j = tid >> 3, k = tid & 7;
        int jj = j < k ? j : k, kk = j < k ? k : j;
        sMf[tid] = g_M[jj*8 + kk];
    }
    if (tid >= 64 && tid < 72) sTv[tid - 64] = g_T[tid - 64];
    __syncthreads();
    if (tid < 64) {
        const float invN = 1.f / 147456.f;
        const float* w = &sW1[tid*8];
        float ts = 0.f, y2 = 0.f;
#pragma unroll
        for (int k = 0; k < 8; k++) ts = fmaf(w[k], sTv[k], ts);
#pragma unroll
        for (int j = 0; j < 8; j++) {
            float rj = 0.f;
#pragma unroll
            for (int k = 0; k < 8; k++) rj = fmaf(w[k], sMf[j*8 + k], rj);
            y2 = fmaf(w[j], rj, y2);
        }
        float mean = ts * invN;
        float var  = y2 * invN - mean*mean;
        float sc = __ldg(&bn1g[tid]) * rsqrtf(var + 1e-5f);
        sS[tid] = sc;
        sT[tid] = __ldg(&bn1b[tid]) - mean * sc;
    }
    __syncthreads();
    // activation: thread owns an l-PAIR (x window in 9 regs) x 16 i's
    {
        int lp = tid & 63, ig = tid >> 6;   // 64 l-pairs x 4 i-groups
        int lb = lp << 1;
        float xw[9];
#pragma unroll
        for (int k = 0; k < 9; k++) xw[k] = sX[lb + k];
#pragma unroll
        for (int ii = 0; ii < 16; ii++) {
            int i = ig*16 + ii;
            const float* wr = &sW1[i*8];
            float a0 = 0.f, a1 = 0.f;
#pragma unroll
            for (int k = 0; k < 8; k++) {
                float w = wr[k];
                a0 = fmaf(w, xw[k], a0);
                a1 = fmaf(w, xw[k + 1], a1);
            }
            float sc = sS[i], sh = sT[i];
            a0 = fmaf(a0, sc, sh);
            a1 = fmaf(a1, sc, sh);
            *(float2*)&sA[i*132 + lb] = make_float2(gelu(a0), gelu(a1));
        }
    }
    __syncthreads();
    // conv2 partial GEMM: thread = (d-pair, l-quad of 32); A loads amortized over 2 d's
    int dp = tid >> 5, lg = tid & 31;
    int d0 = dp*2, d1 = d0 + 1;
    float4 acc0 = make_float4(0.f, 0.f, 0.f, 0.f);
    float4 acc1 = make_float4(0.f, 0.f, 0.f, 0.f);
    const float4* wrow0 = (const float4*)&sW2c[d0*64];
    const float4* wrow1 = (const float4*)&sW2c[d1*64];
    const float* ab0 = &sA[lg*4];
#pragma unroll
    for (int j = 0; j < 16; j++) {
        float4 w40 = wrow0[j];
        float4 w41 = wrow1[j];
        const float* ab = ab0 + j*4*132;
        float4 a0 = *(const float4*)(ab);
        float4 a1 = *(const float4*)(ab + 132);
        float4 a2 = *(const float4*)(ab + 264);
        float4 a3 = *(const float4*)(ab + 396);
        acc0.x = fmaf(w40.x,a0.x, fmaf(w40.y,a1.x, fmaf(w40.z,a2.x, fmaf(w40.w,a3.x, acc0.x))));
        acc0.y = fmaf(w40.x,a0.y, fmaf(w40.y,a1.y, fmaf(w40.z,a2.y, fmaf(w40.w,a3.y, acc0.y))));
        acc0.z = fmaf(w40.x,a0.z, fmaf(w40.y,a1.z, fmaf(w40.z,a2.z, fmaf(w40.w,a3.z, acc0.z))));
        acc0.w = fmaf(w40.x,a0.w, fmaf(w40.y,a1.w, fmaf(w40.z,a2.w, fmaf(w40.w,a3.w, acc0.w))));
        acc1.x = fmaf(w41.x,a0.x, fmaf(w41.y,a1.x, fmaf(w41.z,a2.x, fmaf(w41.w,a3.x, acc1.x))));
        acc1.y = fmaf(w41.x,a0.y, fmaf(w41.y,a1.y, fmaf(w41.z,a2.y, fmaf(w41.w,a3.y, acc1.y))));
        acc1.z = fmaf(w41.x,a0.z, fmaf(w41.y,a1.z, fmaf(w41.z,a2.z, fmaf(w41.w,a3.z, acc1.z))));
        acc1.w = fmaf(w41.x,a0.w, fmaf(w41.y,a1.w, fmaf(w41.z,a2.w, fmaf(w41.w,a3.w, acc1.w))));
    }
    int baseo = (b*LL + l0 + lg*4)*DD;
    atomicAdd(&g_h2[baseo + d0     ], acc0.x);
    atomicAdd(&g_h2[baseo + d0 + 16], acc0.y);
    atomicAdd(&g_h2[baseo + d0 + 32], acc0.z);
    atomicAdd(&g_h2[baseo + d0 + 48], acc0.w);
    atomicAdd(&g_h2[baseo + d1     ], acc1.x);
    atomicAdd(&g_h2[baseo + d1 + 16], acc1.y);
    atomicAdd(&g_h2[baseo + d1 + 32], acc1.z);
    atomicAdd(&g_h2[baseo + d1 + 48], acc1.w);
}

// ---------------- inline BN2 stats + spin barrier + bn2+gelu + pos-enc + QKV ----------------
// grid 256 x 256 (all blocks co-resident: <=3.4KB smem); 4 threads/token (2 heads each)
// also re-zeroes its own g_h2 slice after consumption (for the next replay)
__global__ void k_qkv(const float* __restrict__ wq, const float* __restrict__ wk,
                      const float* __restrict__ wv,
                      const float* __restrict__ bn2g, const float* __restrict__ bn2b) {
    __shared__ float sq_[256], sk_[256], sv_[256], s2s[16], s2t[16];
    __shared__ float sS2[16], sQ2[16];
    int tid = threadIdx.x;
    // ---- phase 1: partial BN2 stats over this block's slice of g_h2 ----
    if (tid < 16) { sS2[tid] = 0.f; sQ2[tid] = 0.f; }
    __syncthreads();
    {
        int gid = blockIdx.x*256 + tid;          // 0..65535 float4s
        float4 hv = ((const float4*)g_h2)[gid];
        float s0 = hv.x, s1 = hv.y, s2 = hv.z, s3 = hv.w;
        float q0 = hv.x*hv.x, q1 = hv.y*hv.y, q2 = hv.z*hv.z, q3 = hv.w*hv.w;
#pragma unroll
        for (int off = 4; off <= 16; off <<= 1) {
            s0 += __shfl_down_sync(0xffffffffu, s0, off);
            s1 += __shfl_down_sync(0xffffffffu, s1, off);
            s2 += __shfl_down_sync(0xffffffffu, s2, off);
            s3 += __shfl_down_sync(0xffffffffu, s3, off);
            q0 += __shfl_down_sync(0xffffffffu, q0, off);
            q1 += __shfl_down_sync(0xffffffffu, q1, off);
            q2 += __shfl_down_sync(0xffffffffu, q2, off);
            q3 += __shfl_down_sync(0xffffffffu, q3, off);
        }
        if ((tid & 31) < 4) {
            int db = (tid & 3) * 4;
            atomicAdd(&sS2[db    ], s0); atomicAdd(&sQ2[db    ], q0);
            atomicAdd(&sS2[db + 1], s1); atomicAdd(&sQ2[db + 1], q1);
            atomicAdd(&sS2[db + 2], s2); atomicAdd(&sQ2[db + 2], q2);
            atomicAdd(&sS2[db + 3], s3); atomicAdd(&sQ2[db + 3], q3);
        }
    }
    __syncthreads();
    if (tid < 16) { atomicAdd(&g_s2sum[tid], sS2[tid]); atomicAdd(&g_s2sq[tid], sQ2[tid]); }
    // ---- spin barrier across all 256 resident blocks ----
    __syncthreads();
    if (tid == 0) {
        __threadfence();
        atomicAdd(&g_done2, 1u);
        while (*(volatile unsigned*)&g_done2 < 256u) { }
    }
    __syncthreads();
    __threadfence();
    // ---- phase 2: weights + bn2 finalize ----
    sq_[tid] = __ldg(&wq[tid]); sk_[tid] = __ldg(&wk[tid]); sv_[tid] = __ldg(&wv[tid]);
    if (tid < 16) {
        const float invN = 1.f / 16384.f;
        float mean = g_s2sum[tid] * invN;
        float var  = g_s2sq[tid] * invN - mean*mean;
        float sc = __ldg(&bn2g[tid]) * rsqrtf(var + 1e-5f);
        s2s[tid] = sc;
        s2t[tid] = __ldg(&bn2b[tid]) - mean * sc;
    }
    __syncthreads();
    int sub = tid & 3;
    int t = blockIdx.x*64 + (tid >> 2);
    int l = t & 1023, b = t >> 10;
    float xp[16];
    const float4* hr = (const float4*)&g_h2[t*DD];
    float4* xsr = (float4*)&g_xsrc[t*DD];
#pragma unroll
    for (int i = 0; i < 4; i++) {
        float4 h4 = hr[i];
        float vs[4] = {h4.x, h4.y, h4.z, h4.w};
#pragma unroll
        for (int j = 0; j < 4; j++) {
            int d = i*4 + j;
            float v = gelu(fmaf(vs[j], s2s[d], s2t[d]));
            vs[j] = v; xp[d] = v;
        }
        if (sub == 0) xsr[i] = make_float4(vs[0], vs[1], vs[2], vs[3]);
    }
    // re-zero own g_h2 float4 (this thread's sub slice) for the next replay
    ((float4*)&g_h2[t*DD])[sub] = make_float4(0.f, 0.f, 0.f, 0.f);
    const float divc[8] = {1.f, 0.31622776601683794f, 0.1f, 0.031622776601683794f,
                           0.01f, 0.0031622776601683794f, 0.001f, 0.00031622776601683794f};
    float lf = (float)l;
#pragma unroll
    for (int j = 0; j < 8; j++) {
        float ang = lf * divc[j] * 0.015625f;
        float sv, cv; __sincosf(ang, &sv, &cv);
        xp[2*j]   += sv;
        xp[2*j+1] += cv;
    }
    const float QS = 0.36067376022224085f;  // 0.25 * log2(e)
#pragma unroll
    for (int hh = 0; hh < 2; hh++) {
        int h = sub*2 + hh;
        float q0=0,q1=0,k0=0,k1=0,v0=0,v1=0;
#pragma unroll
        for (int e = 0; e < 16; e++) {
            float xv = xp[e];
            q0 = fmaf(xv, sq_[e*16 + 2*h    ], q0);
            q1 = fmaf(xv, sq_[e*16 + 2*h + 1], q1);
            k0 = fmaf(xv, sk_[e*16 + 2*h    ], k0);
            k1 = fmaf(xv, sk_[e*16 + 2*h + 1], k1);
            v0 = fmaf(xv, sv_[e*16 + 2*h    ], v0);
            v1 = fmaf(xv, sv_[e*16 + 2*h + 1], v1);
        }
        int bh = b*8 + h;
        float* sb = &g_soa[bh*4096];
        int pk = l >> 1, e = l & 1;
        // interleaved: k-int[pk] = (kx_e, kx_o, ky_e, ky_o); v-int at +2048
        sb[pk*4 + e]            = k0;
        sb[pk*4 + 2 + e]        = k1;
        sb[2048 + pk*4 + e]     = v0;
        sb[2048 + pk*4 + 2 + e] = v1;
        ((float2*)g_q)[bh*1024 + l] = make_float2(q0*QS, q1*QS);
    }
}

// ---------------- attention: softmax(q.k/4)@V + bias@V in ONE loop ----------------
// grid 512 = bh(128) x qtile(4 of 256); 256 thr; one q per thread
// pair-interleaved smem: one LDS.128 yields both k-u64s (or both v-u64s)
__global__ void k_attn(const float* __restrict__ rel) {
    __shared__ float4 skI[512], svI[512];
    __shared__ float2 sr0[640], sr1[640];
    __shared__ float sred[16];
    int bx = blockIdx.x;
    int tile = bx & 3, bh = bx >> 2, h = bh & 7, b = bh >> 3;
    int q0 = tile << 8;
    int tid = threadIdx.x;
    const float4* base = (const float4*)&g_soa[bh*4096];
    float4 k0v = base[tid];
    skI[tid] = k0v;
    float mk0 = fmaxf(fabsf(k0v.x), fabsf(k0v.y));
    float mk1 = fmaxf(fabsf(k0v.z), fabsf(k0v.w));
    float4 k1v = base[256 + tid];
    skI[256 + tid] = k1v;
    mk0 = fmaxf(mk0, fmaxf(fabsf(k1v.x), fabsf(k1v.y)));
    mk1 = fmaxf(mk1, fmaxf(fabsf(k1v.z), fabsf(k1v.w)));
    svI[tid]       = base[512 + tid];
    svI[256 + tid] = base[768 + tid];
    // rel pairs, parity-preswapped: srel[i] := rel[(q0+i)*8+h], i in [0,1279)
    for (int s = tid; s < 640; s += 256) {
        int i2 = 2*s;
        float r0 = (i2     < 1279) ? __ldg(&rel[(q0 + i2    )*8 + h]) : 0.f;
        float r1 = (i2 + 1 < 1279) ? __ldg(&rel[(q0 + i2 + 1)*8 + h]) : 0.f;
        float r2 = (i2 + 2 < 1279) ? __ldg(&rel[(q0 + i2 + 2)*8 + h]) : 0.f;
        sr0[s] = make_float2(r1, r0);
        sr1[s] = make_float2(r2, r1);
    }
#pragma unroll
    for (int off = 16; off; off >>= 1) {
        mk0 = fmaxf(mk0, __shfl_xor_sync(0xffffffffu, mk0, off));
        mk1 = fmaxf(mk1, __shfl_xor_sync(0xffffffffu, mk1, off));
    }
    if ((tid & 31) == 0) { sred[tid >> 5] = mk0; sred[8 + (tid >> 5)] = mk1; }
    __syncthreads();
    float K0 = sred[0], K1 = sred[8];
#pragma unroll
    for (int i = 1; i < 8; i++) { K0 = fmaxf(K0, sred[i]); K1 = fmaxf(K1, sred[8+i]); }

    float2 qq = ((const float2*)g_q)[(bh << 10) + q0 + tid];
    float m = fabsf(qq.x)*K0 + fabsf(qq.y)*K1;   // upper bound; shift cancels in acc/l
    u64 qx2 = pk2(qq.x, qq.x), qy2 = pk2(qq.y, qq.y), negm2 = pk2(-m, -m);
    u64 l2 = 0, a0 = 0, a1 = 0, c0 = 0, c1 = 0;
    int p = tid & 1;
    int roff = ((tid - p) >> 1) + 511;
    const float2* srp = p ? sr1 : sr0;
    const longlong2* skp = (const longlong2*)skI;
    const longlong2* svp = (const longlong2*)svI;
#pragma unroll 4
    for (int kk = 0; kk < 512; kk++) {
        longlong2 kp = skp[kk];                   // LDS.128: kx-pair | ky-pair
        longlong2 vp = svp[kk];                   // LDS.128: vx-pair | vy-pair
        u64 s2 = fma2_(qy2, (u64)kp.y, fma2_(qx2, (u64)kp.x, negm2));
        float s0, s1; upk2(s2, s0, s1);
        u64 e2 = pk2(ex2f(s0), ex2f(s1));
        l2 = add2_(l2, e2);
        a0 = fma2_(e2, (u64)vp.x, a0);
        a1 = fma2_(e2, (u64)vp.y, a1);
        u64 r2 = *(const u64*)&srp[roff - kk];
        c0 = fma2_(r2, (u64)vp.x, c0);
        c1 = fma2_(r2, (u64)vp.y, c1);
    }
    float p0, p1;
    upk2(l2, p0, p1); float inv = 1.f / (p0 + p1);
    upk2(a0, p0, p1); float A0 = p0 + p1;
    upk2(a1, p0, p1); float A1 = p0 + p1;
    upk2(c0, p0, p1); float C0 = p0 + p1;
    upk2(c1, p0, p1); float C1 = p0 + p1;
    int ti = b*LL + q0 + tid;
    *(float2*)&g_o[ti*DD + 2*h] =
        make_float2(fmaf(A0, inv, C0), fmaf(A1, inv, C1));
}

// ---------------- LN_attn + res + LN1 + FFN(j-split x4) + res + LN2 + pool + final ----------------
// grid 256 x 256; 4 threads per token; last block computes the classifier output
// and re-zeroes all small accumulators for the next replay
__global__ void k_post(const float* __restrict__ w1, const float* __restrict__ b1,
                       const float* __restrict__ w2, const float* __restrict__ b2,
                       const float* __restrict__ lag, const float* __restrict__ lab,
                       const float* __restrict__ l1g, const float* __restrict__ l1b,
                       const float* __restrict__ l2g, const float* __restrict__ l2b,
                       const float* __restrict__ ow, const float* __restrict__ ob,
                       float* __restrict__ out) {
    __shared__ float sW1T[4096];  // [j][d]
    __shared__ float sW2[4096];   // [j][d]
    __shared__ float sB1[256], sPool[16], sLn[112];
    __shared__ unsigned sLast;
    int tid = threadIdx.x;
    for (int i = tid; i < 4096; i += 256) {
        sW1T[(i & 255)*16 + (i >> 8)] = __ldg(&w1[i]);
        sW2[i] = __ldg(&w2[i]);
    }
    sB1[tid] = __ldg(&b1[tid]);
    if (tid < 16) {
        sPool[tid] = 0.f;
        sLn[tid]      = __ldg(&lag[tid]); sLn[16 + tid] = __ldg(&lab[tid]);
        sLn[32 + tid] = __ldg(&l1g[tid]); sLn[48 + tid] = __ldg(&l1b[tid]);
        sLn[64 + tid] = __ldg(&l2g[tid]); sLn[80 + tid] = __ldg(&l2b[tid]);
        sLn[96 + tid] = __ldg(&b2[tid]);
    }
    __syncthreads();
    int sub = tid & 3;
    int t = blockIdx.x*64 + (tid >> 2);
    float v[16], xs[16], att[16], acc[16];
    const float4* orow = (const float4*)&g_o[t*DD];
    const float4* xrow = (const float4*)&g_xsrc[t*DD];
#pragma unroll
    for (int i = 0; i < 4; i++) {
        float4 f = orow[i]; v[4*i]=f.x; v[4*i+1]=f.y; v[4*i+2]=f.z; v[4*i+3]=f.w;
        float4 g = xrow[i]; xs[4*i]=g.x; xs[4*i+1]=g.y; xs[4*i+2]=g.z; xs[4*i+3]=g.w;
    }
    float mean = 0.f, sq = 0.f;
#pragma unroll
    for (int d = 0; d < 16; d++) { mean += v[d]; sq = fmaf(v[d], v[d], sq); }
    mean *= 0.0625f;
    float rs = rsqrtf(sq*0.0625f - mean*mean + 1e-5f);
    float m2 = 0.f, q2 = 0.f;
#pragma unroll
    for (int d = 0; d < 16; d++) {
        float x1 = xs[d] + fmaf((v[d]-mean)*rs, sLn[d], sLn[16+d]);
        v[d] = x1; m2 += x1; q2 = fmaf(x1, x1, q2);
    }
    m2 *= 0.0625f;
    float rs2 = rsqrtf(q2*0.0625f - m2*m2 + 1e-5f);
#pragma unroll
    for (int d = 0; d < 16; d++)
        att[d] = fmaf((v[d]-m2)*rs2, sLn[32+d], sLn[48+d]);
#pragma unroll
    for (int d = 0; d < 16; d++) acc[d] = 0.f;
    int j0 = sub << 6;
#pragma unroll 2
    for (int jj = 0; jj < 64; jj++) {
        int j = j0 + jj;
        const float4* w1r = (const float4*)&sW1T[j*16];
        float hv = sB1[j];
#pragma unroll
        for (int i = 0; i < 4; i++) {
            float4 w4 = w1r[i];
            hv = fmaf(att[4*i], w4.x, hv); hv = fmaf(att[4*i+1], w4.y, hv);
            hv = fmaf(att[4*i+2], w4.z, hv); hv = fmaf(att[4*i+3], w4.w, hv);
        }
        hv = fmaxf(hv, 0.f);
        const float4* w2r = (const float4*)&sW2[j*16];
#pragma unroll
        for (int i = 0; i < 4; i++) {
            float4 w4 = w2r[i];
            acc[4*i]   = fmaf(hv, w4.x, acc[4*i]);
            acc[4*i+1] = fmaf(hv, w4.y, acc[4*i+1]);
            acc[4*i+2] = fmaf(hv, w4.z, acc[4*i+2]);
            acc[4*i+3] = fmaf(hv, w4.w, acc[4*i+3]);
        }
    }
#pragma unroll
    for (int d = 0; d < 16; d++) {
        acc[d] += __shfl_xor_sync(0xffffffffu, acc[d], 1);
        acc[d] += __shfl_xor_sync(0xffffffffu, acc[d], 2);
    }
    float m3 = 0.f, q3 = 0.f;
#pragma unroll
    for (int d = 0; d < 16; d++) {
        float x2 = att[d] + acc[d] + sLn[96+d];
        v[d] = x2; m3 += x2; q3 = fmaf(x2, x2, q3);
    }
    m3 *= 0.0625f;
    float rs3 = rsqrtf(q3*0.0625f - m3*m3 + 1e-5f);
    if (sub == 0) {
#pragma unroll
        for (int d = 0; d < 16; d++) {
            float fin = fmaf((v[d]-m3)*rs3, sLn[64+d], sLn[80+d]);
            atomicAdd(&sPool[d], fin);
        }
    }
    __syncthreads();
    if (tid < 16) atomicAdd(&g_pool[(blockIdx.x >> 4)*16 + tid], sPool[tid]);
    // ---- completion counter: last block computes the classifier + resets state ----
    __threadfence();
    __syncthreads();
    if (tid == 0) sLast = (atomicAdd(&g_done, 1u) == 255u) ? 1u : 0u;
    __syncthreads();
    if (sLast) {
        if (tid < BB*NCLS) {
            int b = tid / NCLS, n = tid % NCLS;
            float a = __ldg(&ob[n]);
#pragma unroll
            for (int d = 0; d < 16; d++) {
                float pv = atomicAdd(&g_pool[b*16 + d], 0.f);   // coherent read
                a = fmaf(pv * 0.0009765625f, __ldg(&ow[d*NCLS + n]), a);
            }
            out[tid] = a;
        }
        __syncthreads();
        // re-zero all small accumulators for the next graph replay
        g_pool[tid] = 0.f;
        if (tid < 64) g_M[tid] = 0.f;
        if (tid < 8)  g_T[tid] = 0.f;
        if (tid < DD) { g_s2sum[tid] = 0.f; g_s2sq[tid] = 0.f; }
        if (tid == 0) { g_done2 = 0u; __threadfence(); g_done = 0u; }
    }
}

// ---------------- launch ----------------
extern "C" void kernel_launch(void* const* d_in, const int* in_sizes, int n_in,
                              void* d_out, int out_size) {
    const float* x    = (const float*)d_in[0];
    const float* c1w  = (const float*)d_in[1];
    const float* bn1g = (const float*)d_in[3];
    const float* bn1b = (const float*)d_in[4];
    const float* c2w  = (const float*)d_in[5];
    const float* bn2g = (const float*)d_in[7];
    const float* bn2b = (const float*)d_in[8];
    const float* wq   = (const float*)d_in[9];
    const float* wk   = (const float*)d_in[10];
    const float* wv   = (const float*)d_in[11];
    const float* rel  = (const float*)d_in[12];
    const float* lag  = (const float*)d_in[13];
    const float* lab  = (const float*)d_in[14];
    const float* l1g  = (const float*)d_in[15];
    const float* l1b  = (const float*)d_in[16];
    const float* fw1  = (const float*)d_in[17];
    const float* fb1  = (const float*)d_in[18];
    const float* fw2  = (const float*)d_in[19];
    const float* fb2  = (const float*)d_in[20];
    const float* l2g  = (const float*)d_in[21];
    const float* l2b  = (const float*)d_in[22];
    const float* ow   = (const float*)d_in[23];
    const float* ob   = (const float*)d_in[24];

    k_pre   <<<180, 256>>>(x, c1w, c2w);
    k_fused <<<1152, 256>>>(x, c1w, bn1g, bn1b);
    k_qkv   <<<256, 256>>>(wq, wk, wv, bn2g, bn2b);
    k_attn  <<<512, 256>>>(rel);
    k_post  <<<256, 256>>>(fw1, fb1, fw2, fb2, lag, lab, l1g, l1b, l2g, l2b,
                           ow, ob, (float*)d_out);
}